// round 1
// baseline (speedup 1.0000x reference)
#include <cuda_runtime.h>
#include <math.h>

#define C_DIM 1024
#define NQ 10            // gated queries (ref has NQ+1 = 11 query rows)
#define MAXN 100000
#define K1_RPB 64        // rows per block in pass 1 (8 warps x 8 rows)
#define K2_TILE 128      // rows per block in pass 2
#define K2_MAXBLOCKS ((MAXN + K2_TILE - 1) / K2_TILE)

// ---- scratch (static device memory; no allocations) ----
__device__ float g_Qd[NQ * C_DIM];                       // Qn[q] - Qn[NQ]
__device__ float g_logits[(size_t)NQ * MAXN];            // [q][n], 4 MB
__device__ float g_M[NQ];                                // per-q max logit
__device__ float g_Z[NQ];                                // per-q softmax denom
__device__ float g_partial[(size_t)K2_MAXBLOCKS * C_DIM];// pass-2 partials
__device__ float g_pooled[C_DIM];

__device__ __forceinline__ void atomicMaxFloat(float* addr, float val) {
    int old = __float_as_int(*addr);
    while (__int_as_float(old) < val) {
        int assumed = old;
        old = atomicCAS((int*)addr, assumed, __float_as_int(val));
        if (old == assumed) break;
    }
}

// ============================================================
// K0: normalize Q rows, build Qd = Qn[q]-Qn[NQ]; init M/Z/pooled
// ============================================================
__global__ void k0_prep(const float* __restrict__ Q) {
    __shared__ float s_norm[NQ + 1];
    __shared__ float s_red[128];
    int t = threadIdx.x;
    for (int q = 0; q < NQ + 1; q++) {
        float ss = 0.f;
        for (int c = t; c < C_DIM; c += 128) {
            float v = Q[q * C_DIM + c];
            ss = fmaf(v, v, ss);
        }
        s_red[t] = ss;
        __syncthreads();
        for (int s = 64; s > 0; s >>= 1) {
            if (t < s) s_red[t] += s_red[t + s];
            __syncthreads();
        }
        if (t == 0) s_norm[q] = fmaxf(sqrtf(s_red[0]), 1e-12f);
        __syncthreads();
    }
    float invL = 1.0f / s_norm[NQ];
    for (int q = 0; q < NQ; q++) {
        float invq = 1.0f / s_norm[q];
        for (int c = t; c < C_DIM; c += 128)
            g_Qd[q * C_DIM + c] = Q[q * C_DIM + c] * invq - Q[NQ * C_DIM + c] * invL;
    }
    if (t < NQ) { g_M[t] = -1e30f; g_Z[t] = 0.f; }
    for (int c = t; c < C_DIM; c += 128) g_pooled[c] = 0.f;
}

// ============================================================
// K1: logits[q][n] = 100 * (Qd[q] . X[n]) / max(||X[n]||, eps)
// warp-per-8-rows, Qd staged in smem, reused across 8 rows
// ============================================================
__global__ __launch_bounds__(256, 1) void k1_logits(const float* __restrict__ X, int N) {
    __shared__ float s_qd[NQ * C_DIM];          // 40 KB
    __shared__ float s_l[NQ][K1_RPB];           // staged logits for coalesced store
    int t = threadIdx.x;
    for (int i = t; i < NQ * C_DIM; i += 256) s_qd[i] = g_Qd[i];
    __syncthreads();

    int warp = t >> 5, lane = t & 31;
    int row0 = blockIdx.x * K1_RPB + warp * 8;

    float acc[8][NQ + 1];
#pragma unroll
    for (int j = 0; j < 8; j++)
#pragma unroll
        for (int q = 0; q < NQ + 1; q++) acc[j][q] = 0.f;

    bool valid[8];
#pragma unroll
    for (int j = 0; j < 8; j++) valid[j] = (row0 + j) < N;

    const float* xb = X + (size_t)row0 * C_DIM;

    for (int kk = 0; kk < 8; kk++) {
        int cb = kk * 128 + lane * 4;
        float4 xv[8];
#pragma unroll
        for (int j = 0; j < 8; j++)
            xv[j] = valid[j] ? *(const float4*)(xb + (size_t)j * C_DIM + cb)
                             : make_float4(0.f, 0.f, 0.f, 0.f);
        float4 qd[NQ];
#pragma unroll
        for (int q = 0; q < NQ; q++) qd[q] = *(const float4*)&s_qd[q * C_DIM + cb];
#pragma unroll
        for (int j = 0; j < 8; j++) {
            float4 x = xv[j];
            float s = acc[j][NQ];
            s = fmaf(x.x, x.x, s); s = fmaf(x.y, x.y, s);
            s = fmaf(x.z, x.z, s); s = fmaf(x.w, x.w, s);
            acc[j][NQ] = s;
#pragma unroll
            for (int q = 0; q < NQ; q++) {
                float a = acc[j][q];
                a = fmaf(x.x, qd[q].x, a); a = fmaf(x.y, qd[q].y, a);
                a = fmaf(x.z, qd[q].z, a); a = fmaf(x.w, qd[q].w, a);
                acc[j][q] = a;
            }
        }
    }

    // lane reduction (all 88 values)
#pragma unroll
    for (int j = 0; j < 8; j++)
#pragma unroll
        for (int q = 0; q < NQ + 1; q++) {
            float v = acc[j][q];
#pragma unroll
            for (int off = 16; off; off >>= 1)
                v += __shfl_xor_sync(0xffffffffu, v, off);
            acc[j][q] = v;
        }

    if (lane == 0) {
#pragma unroll
        for (int j = 0; j < 8; j++) {
            float rn = fmaxf(sqrtf(acc[j][NQ]), 1e-12f);
            float sc = 100.0f / rn;
#pragma unroll
            for (int q = 0; q < NQ; q++) s_l[q][warp * 8 + j] = acc[j][q] * sc;
        }
    }
    __syncthreads();

    int col0 = blockIdx.x * K1_RPB;
    for (int i = t; i < NQ * K1_RPB; i += 256) {
        int q = i >> 6, c = i & (K1_RPB - 1);
        int n = col0 + c;
        if (n < N) g_logits[(size_t)q * N + n] = s_l[q][c];
    }
}

// ============================================================
// K1.5a: per-q max over logits   (grid = NQ*16 blocks)
// ============================================================
__global__ void k15a_max(int N) {
    int q = blockIdx.x >> 4, part = blockIdx.x & 15;
    const float* l = g_logits + (size_t)q * N;
    float m = -1e30f;
    for (int n = part * 256 + threadIdx.x; n < N; n += 16 * 256)
        m = fmaxf(m, l[n]);
    __shared__ float red[256];
    int t = threadIdx.x;
    red[t] = m;
    __syncthreads();
    for (int s = 128; s > 0; s >>= 1) {
        if (t < s) red[t] = fmaxf(red[t], red[t + s]);
        __syncthreads();
    }
    if (t == 0) atomicMaxFloat(&g_M[q], red[0]);
}

// ============================================================
// K1.5b: Z[q] = sum_n exp(l - M)   (grid = NQ*16 blocks)
// ============================================================
__global__ void k15b_z(int N) {
    int q = blockIdx.x >> 4, part = blockIdx.x & 15;
    const float* l = g_logits + (size_t)q * N;
    float M = g_M[q];
    float s = 0.f;
    for (int n = part * 256 + threadIdx.x; n < N; n += 16 * 256)
        s += __expf(l[n] - M);
    __shared__ float red[256];
    int t = threadIdx.x;
    red[t] = s;
    __syncthreads();
    for (int st = 128; st > 0; st >>= 1) {
        if (t < st) red[t] += red[t + st];
        __syncthreads();
    }
    if (t == 0) atomicAdd(&g_Z[q], red[0]);
}

// ============================================================
// K2: partial[b][c] = sum over block's rows of g[n]*X[n][c]
//     g[n] = (1/NQ) * sum_q exp(l[q][n]-M_q)/Z_q
// thread t owns columns {4t..4t+3} and {512+4t..}
// ============================================================
__global__ __launch_bounds__(128) void k2_wsum(const float* __restrict__ X, int N) {
    __shared__ float s_g[K2_TILE];
    __shared__ float s_m[NQ], s_iz[NQ];
    int t = threadIdx.x;
    int n0 = blockIdx.x * K2_TILE;
    if (t < NQ) { s_m[t] = g_M[t]; s_iz[t] = (1.0f / NQ) / g_Z[t]; }
    __syncthreads();
    int nv = min(K2_TILE, N - n0);
    if (t < nv) {
        int n = n0 + t;
        float gs = 0.f;
#pragma unroll
        for (int q = 0; q < NQ; q++)
            gs = fmaf(__expf(g_logits[(size_t)q * N + n] - s_m[q]), s_iz[q], gs);
        s_g[t] = gs;
    }
    __syncthreads();

    float4 a0 = make_float4(0.f, 0.f, 0.f, 0.f);
    float4 a1 = make_float4(0.f, 0.f, 0.f, 0.f);
    const float* xb = X + (size_t)n0 * C_DIM + 4 * t;

    int r = 0;
    for (; r + 4 <= nv; r += 4) {
        const float* p = xb + (size_t)r * C_DIM;
        float4 x00 = *(const float4*)(p);
        float4 x01 = *(const float4*)(p + 512);
        float4 x10 = *(const float4*)(p + C_DIM);
        float4 x11 = *(const float4*)(p + C_DIM + 512);
        float4 x20 = *(const float4*)(p + 2 * C_DIM);
        float4 x21 = *(const float4*)(p + 2 * C_DIM + 512);
        float4 x30 = *(const float4*)(p + 3 * C_DIM);
        float4 x31 = *(const float4*)(p + 3 * C_DIM + 512);
        float g0 = s_g[r], g1 = s_g[r + 1], g2 = s_g[r + 2], g3 = s_g[r + 3];
        a0.x = fmaf(g0, x00.x, a0.x); a0.y = fmaf(g0, x00.y, a0.y);
        a0.z = fmaf(g0, x00.z, a0.z); a0.w = fmaf(g0, x00.w, a0.w);
        a1.x = fmaf(g0, x01.x, a1.x); a1.y = fmaf(g0, x01.y, a1.y);
        a1.z = fmaf(g0, x01.z, a1.z); a1.w = fmaf(g0, x01.w, a1.w);
        a0.x = fmaf(g1, x10.x, a0.x); a0.y = fmaf(g1, x10.y, a0.y);
        a0.z = fmaf(g1, x10.z, a0.z); a0.w = fmaf(g1, x10.w, a0.w);
        a1.x = fmaf(g1, x11.x, a1.x); a1.y = fmaf(g1, x11.y, a1.y);
        a1.z = fmaf(g1, x11.z, a1.z); a1.w = fmaf(g1, x11.w, a1.w);
        a0.x = fmaf(g2, x20.x, a0.x); a0.y = fmaf(g2, x20.y, a0.y);
        a0.z = fmaf(g2, x20.z, a0.z); a0.w = fmaf(g2, x20.w, a0.w);
        a1.x = fmaf(g2, x21.x, a1.x); a1.y = fmaf(g2, x21.y, a1.y);
        a1.z = fmaf(g2, x21.z, a1.z); a1.w = fmaf(g2, x21.w, a1.w);
        a0.x = fmaf(g3, x30.x, a0.x); a0.y = fmaf(g3, x30.y, a0.y);
        a0.z = fmaf(g3, x30.z, a0.z); a0.w = fmaf(g3, x30.w, a0.w);
        a1.x = fmaf(g3, x31.x, a1.x); a1.y = fmaf(g3, x31.y, a1.y);
        a1.z = fmaf(g3, x31.z, a1.z); a1.w = fmaf(g3, x31.w, a1.w);
    }
    for (; r < nv; r++) {
        const float* p = xb + (size_t)r * C_DIM;
        float4 x0 = *(const float4*)(p);
        float4 x1 = *(const float4*)(p + 512);
        float g = s_g[r];
        a0.x = fmaf(g, x0.x, a0.x); a0.y = fmaf(g, x0.y, a0.y);
        a0.z = fmaf(g, x0.z, a0.z); a0.w = fmaf(g, x0.w, a0.w);
        a1.x = fmaf(g, x1.x, a1.x); a1.y = fmaf(g, x1.y, a1.y);
        a1.z = fmaf(g, x1.z, a1.z); a1.w = fmaf(g, x1.w, a1.w);
    }
    float* pout = g_partial + (size_t)blockIdx.x * C_DIM;
    *(float4*)(pout + 4 * t) = a0;
    *(float4*)(pout + 512 + 4 * t) = a1;
}

// ============================================================
// K2.5: pooled[c] = sum_b partial[b][c]   (grid 64 x 128)
// ============================================================
__global__ void k25_reduce(int nblocks) {
    int cpart = blockIdx.x & 7;
    int bpart = blockIdx.x >> 3;
    int c = cpart * 128 + threadIdx.x;
    float s = 0.f;
    for (int bb = bpart; bb < nblocks; bb += 8)
        s += g_partial[(size_t)bb * C_DIM + c];
    atomicAdd(&g_pooled[c], s);
}

// ============================================================
// K3: out[j] = b[j] + sum_c pooled[c]*W[j][c]   (grid 128 x 256)
// ============================================================
__global__ __launch_bounds__(256) void k3_linear(const float* __restrict__ W,
                                                 const float* __restrict__ bias,
                                                 float* __restrict__ out) {
    int t = threadIdx.x;
    int j0 = blockIdx.x * 8;
    float4 p = *(const float4*)(g_pooled + 4 * t);
    float part[8];
#pragma unroll
    for (int j = 0; j < 8; j++) {
        const float4 w = *(const float4*)(W + (size_t)(j0 + j) * C_DIM + 4 * t);
        part[j] = fmaf(p.x, w.x, fmaf(p.y, w.y, fmaf(p.z, w.z, p.w * w.w)));
    }
#pragma unroll
    for (int j = 0; j < 8; j++)
#pragma unroll
        for (int off = 16; off; off >>= 1)
            part[j] += __shfl_xor_sync(0xffffffffu, part[j], off);
    __shared__ float s_p[8][8];
    int warp = t >> 5, lane = t & 31;
    if (lane == 0)
#pragma unroll
        for (int j = 0; j < 8; j++) s_p[warp][j] = part[j];
    __syncthreads();
    if (t < 8) {
        float s = 0.f;
#pragma unroll
        for (int w = 0; w < 8; w++) s += s_p[w][t];
        out[j0 + t] = s + bias[j0 + t];
    }
}

// ============================================================
extern "C" void kernel_launch(void* const* d_in, const int* in_sizes, int n_in,
                              void* d_out, int out_size) {
    const float* X = (const float*)d_in[0];
    const float* Q = (const float*)d_in[1];
    const float* W = (const float*)d_in[2];
    const float* b = (const float*)d_in[3];
    float* out = (float*)d_out;

    int N = in_sizes[0] / C_DIM;
    if (N > MAXN) N = MAXN;

    int k1_blocks = (N + K1_RPB - 1) / K1_RPB;
    int k2_blocks = (N + K2_TILE - 1) / K2_TILE;

    k0_prep<<<1, 128>>>(Q);
    k1_logits<<<k1_blocks, 256>>>(X, N);
    k15a_max<<<NQ * 16, 256>>>(N);
    k15b_z<<<NQ * 16, 256>>>(N);
    k2_wsum<<<k2_blocks, 128>>>(X, N);
    k25_reduce<<<64, 128>>>(k2_blocks);
    k3_linear<<<128, 256>>>(W, b, out);
}

// round 2
// speedup vs baseline: 1.0746x; 1.0746x over previous
#include <cuda_runtime.h>
#include <math.h>

#define C_DIM 1024
#define NQ 10            // gated queries (ref has NQ+1 = 11 query rows)
#define MAXN 100000
#define K1_RPW 4         // rows per warp in pass 1
#define K1_WARPS 8
#define K1_RPB (K1_RPW * K1_WARPS)   // 32 rows per block
#define K1_MAXBLOCKS ((MAXN + K1_RPB - 1) / K1_RPB)
#define K2_TILE 128      // rows per block in pass 2
#define K2_MAXBLOCKS ((MAXN + K2_TILE - 1) / K2_TILE)

typedef unsigned long long u64;

// ---- scratch (static device memory; no allocations) ----
__device__ float g_Qd[NQ * C_DIM];                        // Qn[q] - Qn[NQ]
__device__ float g_logits[(size_t)NQ * MAXN];             // [q][n], 4 MB
__device__ float g_bmax[(size_t)K1_MAXBLOCKS * NQ];       // per-block max partials
__device__ float g_M[NQ];                                 // per-q max logit
__device__ float g_Z[NQ];                                 // per-q softmax denom
__device__ float g_partial[(size_t)K2_MAXBLOCKS * C_DIM]; // pass-2 partials
__device__ float g_pooled[C_DIM];

// packed 2xfp32 FMA (Blackwell f32x2 pipe: 2 FMAs per issue slot)
__device__ __forceinline__ u64 f2fma(u64 a, u64 b, u64 c) {
    u64 d;
    asm("fma.rn.f32x2 %0, %1, %2, %3;" : "=l"(d) : "l"(a), "l"(b), "l"(c));
    return d;
}
__device__ __forceinline__ float f2sum(u64 v) {
    return __uint_as_float((unsigned)v) + __uint_as_float((unsigned)(v >> 32));
}

// ============================================================
// K0: normalize Q rows, build Qd = Qn[q]-Qn[NQ]; init Z/pooled
// ============================================================
__global__ void k0_prep(const float* __restrict__ Q) {
    __shared__ float s_norm[NQ + 1];
    __shared__ float s_red[128];
    int t = threadIdx.x;
    for (int q = 0; q < NQ + 1; q++) {
        float ss = 0.f;
        for (int c = t; c < C_DIM; c += 128) {
            float v = Q[q * C_DIM + c];
            ss = fmaf(v, v, ss);
        }
        s_red[t] = ss;
        __syncthreads();
        for (int s = 64; s > 0; s >>= 1) {
            if (t < s) s_red[t] += s_red[t + s];
            __syncthreads();
        }
        if (t == 0) s_norm[q] = fmaxf(sqrtf(s_red[0]), 1e-12f);
        __syncthreads();
    }
    float invL = 1.0f / s_norm[NQ];
    for (int q = 0; q < NQ; q++) {
        float invq = 1.0f / s_norm[q];
        for (int c = t; c < C_DIM; c += 128)
            g_Qd[q * C_DIM + c] = Q[q * C_DIM + c] * invq - Q[NQ * C_DIM + c] * invL;
    }
    if (t < NQ) g_Z[t] = 0.f;
    for (int c = t; c < C_DIM; c += 128) g_pooled[c] = 0.f;
}

// ============================================================
// K1: logits[q][n] = 100 * (Qd[q] . X[n]) / max(||X[n]||, eps)
// warp handles 4 rows; packed f32x2 FMA; per-block max partials
// ============================================================
__global__ __launch_bounds__(256, 2) void k1_logits(const float* __restrict__ X, int N) {
    __shared__ float s_qd[NQ * C_DIM];          // 40 KB
    __shared__ float s_l[NQ][K1_RPB];
    int t = threadIdx.x;
    for (int i = t; i < NQ * C_DIM; i += 256) s_qd[i] = g_Qd[i];
    __syncthreads();

    int warp = t >> 5, lane = t & 31;
    int row0 = blockIdx.x * K1_RPB + warp * K1_RPW;

    u64 acc[K1_RPW][NQ];
    u64 nacc[K1_RPW];
#pragma unroll
    for (int j = 0; j < K1_RPW; j++) {
        nacc[j] = 0ull;
#pragma unroll
        for (int q = 0; q < NQ; q++) acc[j][q] = 0ull;
    }

    // clamp row pointers for tail safety (N is 100000 = multiple of 32 in practice)
    const float* xp[K1_RPW];
#pragma unroll
    for (int j = 0; j < K1_RPW; j++) {
        int r = row0 + j;
        if (r >= N) r = N - 1;
        if (r < 0) r = 0;
        xp[j] = X + (size_t)r * C_DIM;
    }

#pragma unroll
    for (int kk = 0; kk < 8; kk++) {
        int cb = kk * 128 + lane * 4;
        ulonglong2 xv[K1_RPW];
#pragma unroll
        for (int j = 0; j < K1_RPW; j++)
            xv[j] = *(const ulonglong2*)(xp[j] + cb);
#pragma unroll
        for (int j = 0; j < K1_RPW; j++) {
            nacc[j] = f2fma(xv[j].x, xv[j].x, nacc[j]);
            nacc[j] = f2fma(xv[j].y, xv[j].y, nacc[j]);
        }
#pragma unroll
        for (int q = 0; q < NQ; q++) {
            ulonglong2 qv = *(const ulonglong2*)&s_qd[q * C_DIM + cb];
#pragma unroll
            for (int j = 0; j < K1_RPW; j++) {
                acc[j][q] = f2fma(xv[j].x, qv.x, acc[j][q]);
                acc[j][q] = f2fma(xv[j].y, qv.y, acc[j][q]);
            }
        }
    }

    // lane reduction + scale + stage
#pragma unroll
    for (int j = 0; j < K1_RPW; j++) {
        float ns = f2sum(nacc[j]);
        float dot[NQ];
#pragma unroll
        for (int q = 0; q < NQ; q++) dot[q] = f2sum(acc[j][q]);
#pragma unroll
        for (int off = 16; off; off >>= 1) {
            ns += __shfl_xor_sync(0xffffffffu, ns, off);
#pragma unroll
            for (int q = 0; q < NQ; q++)
                dot[q] += __shfl_xor_sync(0xffffffffu, dot[q], off);
        }
        if (lane == 0) {
            int slot = warp * K1_RPW + j;
            if (row0 + j < N) {
                float sc = 100.0f / fmaxf(sqrtf(ns), 1e-12f);
#pragma unroll
                for (int q = 0; q < NQ; q++) s_l[q][slot] = dot[q] * sc;
            } else {
#pragma unroll
                for (int q = 0; q < NQ; q++) s_l[q][slot] = -1e30f;
            }
        }
    }
    __syncthreads();

    // per-block max partial per q
    if (t < NQ) {
        float m = -1e30f;
#pragma unroll
        for (int c = 0; c < K1_RPB; c++) m = fmaxf(m, s_l[t][c]);
        g_bmax[(size_t)blockIdx.x * NQ + t] = m;
    }

    // coalesced logit store
    int col0 = blockIdx.x * K1_RPB;
    for (int i = t; i < NQ * K1_RPB; i += 256) {
        int q = i >> 5, c = i & (K1_RPB - 1);
        int n = col0 + c;
        if (n < N) g_logits[(size_t)q * N + n] = s_l[q][c];
    }
}

// ============================================================
// K1m: merge per-block maxes -> g_M  (1 block, warp per q)
// ============================================================
__global__ void k1_merge(int nblocks) {
    int q = threadIdx.x >> 5, lane = threadIdx.x & 31;
    if (q >= NQ) return;
    float m = -1e30f;
    for (int b = lane; b < nblocks; b += 32)
        m = fmaxf(m, g_bmax[(size_t)b * NQ + q]);
#pragma unroll
    for (int off = 16; off; off >>= 1)
        m = fmaxf(m, __shfl_xor_sync(0xffffffffu, m, off));
    if (lane == 0) g_M[q] = m;
}

// ============================================================
// K1.5b: Z[q] = sum_n exp(l - M)   (grid = NQ*16 blocks)
// ============================================================
__global__ void k15b_z(int N) {
    int q = blockIdx.x >> 4, part = blockIdx.x & 15;
    const float* l = g_logits + (size_t)q * N;
    float M = g_M[q];
    float s = 0.f;
    int n4 = N >> 2;
    for (int i = part * 256 + threadIdx.x; i < n4; i += 16 * 256) {
        float4 v = *(const float4*)(l + 4 * i);
        s += __expf(v.x - M) + __expf(v.y - M) + __expf(v.z - M) + __expf(v.w - M);
    }
    // tail
    for (int n = 4 * n4 + part * 256 + threadIdx.x; n < N; n += 16 * 256)
        s += __expf(l[n] - M);
    __shared__ float red[256];
    int t = threadIdx.x;
    red[t] = s;
    __syncthreads();
    for (int st = 128; st > 0; st >>= 1) {
        if (t < st) red[t] += red[t + st];
        __syncthreads();
    }
    if (t == 0) atomicAdd(&g_Z[q], red[0]);
}

// ============================================================
// K2: partial[b][c] = sum over block's 128 rows of g[n]*X[n][c]
//     g[n] = (1/NQ) * sum_q exp(l[q][n]-M_q)/Z_q
// 256 threads, thread t owns cols 4t..4t+3; 8-row batches (MLP=8)
// ============================================================
__global__ __launch_bounds__(256) void k2_wsum(const float* __restrict__ X, int N) {
    __shared__ float s_g[K2_TILE];
    __shared__ float s_m[NQ], s_iz[NQ];
    int t = threadIdx.x;
    int n0 = blockIdx.x * K2_TILE;
    if (t < NQ) { s_m[t] = g_M[t]; s_iz[t] = (1.0f / NQ) / g_Z[t]; }
    __syncthreads();
    int nv = min(K2_TILE, N - n0);
    if (t < K2_TILE) {
        float gs = 0.f;
        if (t < nv) {
            int n = n0 + t;
#pragma unroll
            for (int q = 0; q < NQ; q++)
                gs = fmaf(__expf(g_logits[(size_t)q * N + n] - s_m[q]), s_iz[q], gs);
        }
        s_g[t] = gs;
    }
    __syncthreads();

    float4 a = make_float4(0.f, 0.f, 0.f, 0.f);
    const float* xb = X + (size_t)n0 * C_DIM + 4 * t;

    int r = 0;
    for (; r + 8 <= nv; r += 8) {
        float4 x[8];
#pragma unroll
        for (int i = 0; i < 8; i++)
            x[i] = *(const float4*)(xb + (size_t)(r + i) * C_DIM);
#pragma unroll
        for (int i = 0; i < 8; i++) {
            float g = s_g[r + i];
            a.x = fmaf(g, x[i].x, a.x); a.y = fmaf(g, x[i].y, a.y);
            a.z = fmaf(g, x[i].z, a.z); a.w = fmaf(g, x[i].w, a.w);
        }
    }
    for (; r < nv; r++) {
        float4 x = *(const float4*)(xb + (size_t)r * C_DIM);
        float g = s_g[r];
        a.x = fmaf(g, x.x, a.x); a.y = fmaf(g, x.y, a.y);
        a.z = fmaf(g, x.z, a.z); a.w = fmaf(g, x.w, a.w);
    }
    *(float4*)(g_partial + (size_t)blockIdx.x * C_DIM + 4 * t) = a;
}

// ============================================================
// K2.5: pooled[c] = sum_b partial[b][c]   (grid 64 x 128)
// ============================================================
__global__ void k25_reduce(int nblocks) {
    int cpart = blockIdx.x & 7;
    int bpart = blockIdx.x >> 3;
    int c = cpart * 128 + threadIdx.x;
    float s = 0.f;
    for (int bb = bpart; bb < nblocks; bb += 8)
        s += g_partial[(size_t)bb * C_DIM + c];
    atomicAdd(&g_pooled[c], s);
}

// ============================================================
// K3: out[j] = b[j] + sum_c pooled[c]*W[j][c]   (grid 128 x 256)
// ============================================================
__global__ __launch_bounds__(256) void k3_linear(const float* __restrict__ W,
                                                 const float* __restrict__ bias,
                                                 float* __restrict__ out) {
    int t = threadIdx.x;
    int j0 = blockIdx.x * 8;
    float4 p = *(const float4*)(g_pooled + 4 * t);
    float part[8];
#pragma unroll
    for (int j = 0; j < 8; j++) {
        const float4 w = *(const float4*)(W + (size_t)(j0 + j) * C_DIM + 4 * t);
        part[j] = fmaf(p.x, w.x, fmaf(p.y, w.y, fmaf(p.z, w.z, p.w * w.w)));
    }
#pragma unroll
    for (int j = 0; j < 8; j++)
#pragma unroll
        for (int off = 16; off; off >>= 1)
            part[j] += __shfl_xor_sync(0xffffffffu, part[j], off);
    __shared__ float s_p[8][8];
    int warp = t >> 5, lane = t & 31;
    if (lane == 0)
#pragma unroll
        for (int j = 0; j < 8; j++) s_p[warp][j] = part[j];
    __syncthreads();
    if (t < 8) {
        float s = 0.f;
#pragma unroll
        for (int w = 0; w < 8; w++) s += s_p[w][t];
        out[j0 + t] = s + bias[j0 + t];
    }
}

// ============================================================
extern "C" void kernel_launch(void* const* d_in, const int* in_sizes, int n_in,
                              void* d_out, int out_size) {
    const float* X = (const float*)d_in[0];
    const float* Q = (const float*)d_in[1];
    const float* W = (const float*)d_in[2];
    const float* b = (const float*)d_in[3];
    float* out = (float*)d_out;

    int N = in_sizes[0] / C_DIM;
    if (N > MAXN) N = MAXN;

    int k1_blocks = (N + K1_RPB - 1) / K1_RPB;
    int k2_blocks = (N + K2_TILE - 1) / K2_TILE;

    k0_prep<<<1, 128>>>(Q);
    k1_logits<<<k1_blocks, 256>>>(X, N);
    k1_merge<<<1, NQ * 32>>>(k1_blocks);
    k15b_z<<<NQ * 16, 256>>>(N);
    k2_wsum<<<k2_blocks, 256>>>(X, N);
    k25_reduce<<<64, 128>>>(k2_blocks);
    k3_linear<<<128, 256>>>(W, b, out);
}